// round 11
// baseline (speedup 1.0000x reference)
#include <cuda_runtime.h>
#include <math.h>

// ---------------- static device scratch (no allocations allowed) ----------------
#define NK 512
#define BATCH 4096
#define WPB 32                        // windows per conv2 batch
#define C2T 512                       // conv2 threads per block (WPB*16)
#define NB  (BATCH * 25 / WPB)        // 3200 batches
#define NSLICE 8                      // add_lut row slices (64 rows each)

__device__ float          g_cs[NK];
__device__ int            g_order[NK];
__device__ float          g_cent[NK];
__device__ unsigned short g_add16[NK * NK];        // add_lut as u16 (512KB)
__device__ unsigned short g_P1[25 * NK * 8];
__device__ unsigned short g_P2[150 * NK * 16];
__device__ unsigned short g_bias1[NK * 8];
__device__ unsigned short g_bias2[NK * 16];
__device__ unsigned short g_relu[NK];
__device__ unsigned short g_sym[BATCH * 32 * 32];
__device__ unsigned short g_x1[BATCH * 14 * 14 * 6];
__device__ unsigned short g_x2[BATCH * 5 * 5 * 16];

// ---------------- prep: stable sort of centroids ----------------
__global__ void k_sortcent(const float* __restrict__ centroid_lut) {
    __shared__ float c[NK];
    int t = threadIdx.x;
    c[t] = centroid_lut[t];
    __syncthreads();
    float ci = c[t];
    int rank = 0;
    for (int j = 0; j < NK; j++) {
        float cj = c[j];
        rank += (cj < ci) || (cj == ci && j < t);
    }
    g_cs[rank]    = ci;
    g_order[rank] = t;
    g_cent[t]     = ci;
}

// ---------------- prep: packed LUT tables ----------------
__global__ void k_prep(const int* __restrict__ conv_lut, const int* __restrict__ add_lut,
                       const int* __restrict__ c1w, const int* __restrict__ c2w,
                       const int* __restrict__ b1, const int* __restrict__ b2,
                       const int* __restrict__ relu) {
    int i = blockIdx.x * blockDim.x + threadIdx.x;
    if (i < NK * NK) { g_add16[i] = (unsigned short)add_lut[i]; return; }
    i -= NK * NK;
    if (i < 25 * NK * 8) {
        int oc = i & 7; int s = (i >> 3) & (NK - 1); int j = i >> 12;
        int occ = oc < 6 ? oc : 5;
        g_P1[i] = (unsigned short)conv_lut[s * NK + c1w[j * 6 + occ]];
        return;
    }
    i -= 25 * NK * 8;
    if (i < 150 * NK * 16) {
        int oc = i & 15; int s = (i >> 4) & (NK - 1); int j = i >> 13;
        g_P2[i] = (unsigned short)conv_lut[s * NK + c2w[j * 16 + oc]];
        return;
    }
    i -= 150 * NK * 16;
    if (i < NK * 8) {
        int oc = i & 7; int s = i >> 3; int occ = oc < 6 ? oc : 5;
        g_bias1[i] = (unsigned short)b1[s * 6 + occ];
        return;
    }
    i -= NK * 8;
    if (i < NK * 16) { g_bias2[i] = (unsigned short)b2[i]; return; }
    i -= NK * 16;
    if (i < NK) g_relu[i] = (unsigned short)relu[i];
}

// ---------------- discretize ----------------
__global__ void k_disc(const float* __restrict__ x) {
    __shared__ float cs[NK];
    __shared__ int   ord[NK];
    int t = threadIdx.x;
    for (int i = t; i < NK; i += blockDim.x) { cs[i] = g_cs[i]; ord[i] = g_order[i]; }
    __syncthreads();
    int idx = blockIdx.x * blockDim.x + t;
    float v = x[idx];
    int lo = 0, hi = NK;
    #pragma unroll
    for (int it = 0; it < 9; it++) {
        int m = (lo + hi) >> 1;
        if (cs[m] < v) lo = m + 1; else hi = m;
    }
    int l = lo - 1; if (l < 0) l = 0;
    int h = lo;     if (h > NK - 1) h = NK - 1;
    float dl = fabsf(v - cs[l]);
    float dh = fabsf(v - cs[h]);
    g_sym[idx] = (unsigned short)ord[(dl <= dh) ? l : h];
}

// ---------------- conv1: register bitonic sort + LUT fold ----------------
__global__ void __launch_bounds__(128) k_conv1() {
    int id  = blockIdx.x * 128 + threadIdx.x;
    int oc  = id % 6;
    int win = id / 6;
    int b   = win / 196;
    int r   = win % 196;
    int oy  = r / 14, ox = r % 14;

    const unsigned short* base = g_sym + (b * 32 + oy * 2) * 32 + ox * 2;
    unsigned v[32];
    #pragma unroll
    for (int ky = 0; ky < 5; ky++)
        #pragma unroll
        for (int kx = 0; kx < 5; kx++) {
            unsigned s = base[ky * 32 + kx];
            v[ky * 5 + kx] = g_P1[((ky * 5 + kx) * NK + s) * 8 + oc];
        }
    #pragma unroll
    for (int i = 25; i < 32; i++) v[i] = 0xFFFFu;

    #pragma unroll
    for (int k2 = 2; k2 <= 32; k2 <<= 1) {
        #pragma unroll
        for (int j = k2 >> 1; j > 0; j >>= 1) {
            #pragma unroll
            for (int i = 0; i < 32; i++) {
                int l = i ^ j;
                if (l > i) {
                    bool up = ((i & k2) == 0);
                    unsigned a = v[i], c = v[l];
                    unsigned mn = a < c ? a : c;
                    unsigned mx = a < c ? c : a;
                    v[i] = up ? mn : mx;
                    v[l] = up ? mx : mn;
                }
            }
        }
    }

    unsigned acc = v[0];
    #pragma unroll
    for (int i = 1; i < 25; i++) acc = g_add16[v[i] * NK + acc];

    unsigned t2 = g_bias1[acc * 8 + oc];
    g_x1[((b * 14 + oy) * 14 + ox) * 6 + oc] = g_relu[t2];
}

// ---------------- conv2: persistent, add_lut slices in SMEM ----------------
// 148 blocks x 512 threads, 1 chain/thread/batch.
// smem: tbl 64KB | hist 128KB (nibble counts, per-thread column) | syms 9.5KB.
// Fold: FIXED-trip inner loop (warp-max count via redux) with a fully
// predicated step body -> no per-iteration divergence machinery.
// Slice reloads register-prefetched so the L2 transfer overlaps the fold.
__global__ void __launch_bounds__(C2T, 1) k_conv2p() {
    extern __shared__ unsigned char sm[];
    unsigned short* tbl  = (unsigned short*)sm;                        // 65536 B
    unsigned int*   hist = (unsigned int*)(sm + 65536);                // 131072 B
    unsigned short* syms = (unsigned short*)(sm + 65536 + 131072);     // 9728 B
    int tid = threadIdx.x;
    int win = tid >> 4, oc = tid & 15;
    unsigned int* hcol = hist + tid;

    for (int batch = blockIdx.x; batch < NB; batch += gridDim.x) {
        // zero own hist column (private: no sync needed)
        #pragma unroll
        for (int g = 0; g < 64; g++) hcol[g * C2T] = 0;

        // cooperative sym staging for WPB windows
        for (int i = tid; i < WPB * 150; i += C2T) {
            int w = i / 150, j = i % 150;
            int wg = batch * WPB + w;
            int b = wg / 25, p = wg % 25;
            int oy = p / 5, ox = p % 5;
            int kk = j / 6, c = j % 6;
            int ky = kk / 5, kx = kk % 5;
            syms[w * 152 + j] =
                g_x1[((b * 14 + oy * 2 + ky) * 14 + (ox * 2 + kx)) * 6 + c];
        }

        // prefetch slice 0 into registers (overlaps staging barrier + phase A)
        uint4 pf[8];
        {
            const uint4* src = (const uint4*)(g_add16);
            #pragma unroll
            for (int i = 0; i < 8; i++) pf[i] = src[i * C2T + tid];
        }
        __syncthreads();

        // phase A: product gather (MLP=10) + nibble histogram + group mask
        //          + per-range value counts packed in rcnt (8 x u8)
        const unsigned short* sy = syms + win * 152;
        unsigned long long mask = 0ull;
        unsigned long long rcnt = 0ull;
        #pragma unroll 1
        for (int j0 = 0; j0 < 150; j0 += 10) {
            unsigned sv[10];
            #pragma unroll
            for (int u = 0; u < 10; u++) sv[u] = sy[j0 + u];
            unsigned vv[10];
            #pragma unroll
            for (int u = 0; u < 10; u++)
                vv[u] = g_P2[((j0 + u) * NK + sv[u]) * 16 + oc];
            #pragma unroll
            for (int u = 0; u < 10; u++) {
                unsigned v = vv[u];
                hcol[(v >> 3) * C2T] += 1u << (4 * (v & 7));
                mask |= 1ull << (v >> 3);
                rcnt += 1ull << (8 * (v >> 6));
            }
        }

        // fold in ascending order across NSLICE row-ranges of the add table
        unsigned acc = 0xFFFFFFFFu;                     // sentinel: first value
        unsigned w = 0;
        int g = 0;
        for (int r = 0; r < NSLICE; r++) {
            __syncthreads();                            // prior fold / phase A done
            {   // commit prefetched slice r to smem
                uint4* dst = (uint4*)tbl;
                #pragma unroll
                for (int i = 0; i < 8; i++) dst[i * C2T + tid] = pf[i];
            }
            __syncthreads();
            if (r + 1 < NSLICE) {                       // prefetch slice r+1 (hidden under fold)
                const uint4* src = (const uint4*)(g_add16 + (r + 1) * 32768);
                #pragma unroll
                for (int i = 0; i < 8; i++) pf[i] = src[i * C2T + tid];
            }

            // split off this range's groups (r==7 covers all remaining; avoids 1<<64)
            unsigned long long cur =
                (r == NSLICE - 1) ? mask : (mask & ((1ull << (8 * (r + 1))) - 1ull));
            mask &= ~cur;

            // fixed trip count: warp-max of this lane's count in range r
            unsigned myc   = (unsigned)((rcnt >> (8 * r)) & 255u);
            unsigned trips = __reduce_max_sync(0xFFFFFFFFu, myc);

            #pragma unroll 1
            for (unsigned s = 0; s < trips; s++) {
                // predicated group pull (no divergent branch needed)
                int gn = __ffsll((long long)cur) - 1;   // -1 when cur empty
                bool pull = (w == 0) && (gn >= 0);
                unsigned wnew = hcol[(pull ? gn : g) * C2T];   // always-safe addr
                if (pull) { g = gn; cur &= cur - 1ull; w = wnew; }
                bool act = (w != 0);
                int ff   = __ffs((int)w);               // 0 iff w==0
                int slot = (ff > 0) ? ((ff - 1) >> 2) : 0;   // SEL, no branch
                unsigned v  = (unsigned)(g * 8 + slot);
                unsigned a  = acc & 511u;               // sentinel-safe index
                unsigned nv = tbl[((v & 63u) << 9) + a];
                unsigned na = (acc > 511u) ? v : nv;
                if (act) { w -= 1u << (slot << 2); acc = na; }
            }
        }

        unsigned t2 = g_bias2[acc * 16 + oc];
        int wg = batch * WPB + win;
        g_x2[wg * 16 + oc] = g_relu[t2];
        __syncthreads();                                // smem reuse next batch
    }
}

// ---------------- FC stack + softmax ----------------
__global__ void __launch_bounds__(128) k_fc(
    const float* __restrict__ w1, const float* __restrict__ fb1,
    const float* __restrict__ w2, const float* __restrict__ fb2,
    const float* __restrict__ w3, const float* __restrict__ fb3,
    float* __restrict__ out) {
    __shared__ __align__(16) float feat[400];
    __shared__ __align__(16) float h1[120];
    __shared__ __align__(16) float h2[84];
    __shared__ float lg[10];
    int b = blockIdx.x, t = threadIdx.x;

    for (int i = t; i < 400; i += 128) {
        int c = i / 25, r = i % 25;
        unsigned s = g_x2[(b * 25 + r) * 16 + c];
        feat[i] = g_cent[s];
    }
    __syncthreads();

    if (t < 120) {
        float acc = fb1[t];
        const float4* wr = (const float4*)(w1 + t * 400);
        const float4* fr = (const float4*)feat;
        #pragma unroll 5
        for (int k = 0; k < 100; k++) {
            float4 a = wr[k], f = fr[k];
            acc += a.x * f.x + a.y * f.y + a.z * f.z + a.w * f.w;
        }
        h1[t] = 1.f / (1.f + expf(-acc));
    }
    __syncthreads();
    if (t < 84) {
        float acc = fb2[t];
        const float4* wr = (const float4*)(w2 + t * 120);
        const float4* fr = (const float4*)h1;
        #pragma unroll 5
        for (int k = 0; k < 30; k++) {
            float4 a = wr[k], f = fr[k];
            acc += a.x * f.x + a.y * f.y + a.z * f.z + a.w * f.w;
        }
        h2[t] = 1.f / (1.f + expf(-acc));
    }
    __syncthreads();
    if (t < 10) {
        float acc = fb3[t];
        const float4* wr = (const float4*)(w3 + t * 84);
        const float4* fr = (const float4*)h2;
        #pragma unroll
        for (int k = 0; k < 21; k++) {
            float4 a = wr[k], f = fr[k];
            acc += a.x * f.x + a.y * f.y + a.z * f.z + a.w * f.w;
        }
        lg[t] = acc;
    }
    __syncthreads();
    if (t < 10) {
        float m = lg[0];
        #pragma unroll
        for (int i = 1; i < 10; i++) m = fmaxf(m, lg[i]);
        float s = 0.f;
        #pragma unroll
        for (int i = 0; i < 10; i++) s += expf(lg[i] - m);
        out[b * 10 + t] = expf(lg[t] - m) / s;
    }
}

// ---------------- launch ----------------
extern "C" void kernel_launch(void* const* d_in, const int* in_sizes, int n_in,
                              void* d_out, int out_size) {
    const float* x        = (const float*)d_in[0];
    const float* cent     = (const float*)d_in[1];
    const int*   c1w      = (const int*)d_in[2];
    const int*   c2w      = (const int*)d_in[3];
    const int*   conv_lut = (const int*)d_in[4];
    const int*   add_lut  = (const int*)d_in[5];
    const int*   b1l      = (const int*)d_in[6];
    const int*   b2l      = (const int*)d_in[7];
    const int*   relu     = (const int*)d_in[8];
    const float* w1  = (const float*)d_in[9];
    const float* fb1 = (const float*)d_in[10];
    const float* w2  = (const float*)d_in[11];
    const float* fb2 = (const float*)d_in[12];
    const float* w3  = (const float*)d_in[13];
    const float* fb3 = (const float*)d_in[14];
    float* out = (float*)d_out;

    const int SMEM_C2 = 65536 + 131072 + 9728;   // 206336 B
    cudaFuncSetAttribute(k_conv2p, cudaFuncAttributeMaxDynamicSharedMemorySize, SMEM_C2);

    k_sortcent<<<1, 512>>>(cent);

    const int prepN = NK * NK + 25 * NK * 8 + 150 * NK * 16 + NK * 8 + NK * 16 + NK;
    k_prep<<<(prepN + 255) / 256, 256>>>(conv_lut, add_lut, c1w, c2w, b1l, b2l, relu);

    k_disc<<<(BATCH * 1024) / 256, 256>>>(x);
    k_conv1<<<(BATCH * 196 * 6) / 128, 128>>>();
    k_conv2p<<<148, C2T, SMEM_C2>>>();
    k_fc<<<BATCH, 128>>>(w1, fb1, w2, fb2, w3, fb3, out);
}

// round 12
// speedup vs baseline: 1.0447x; 1.0447x over previous
#include <cuda_runtime.h>
#include <math.h>

// ---------------- static device scratch (no allocations allowed) ----------------
#define NK 512
#define BATCH 4096
#define WPB 32                        // windows per conv2 batch
#define C2T 512                       // conv2 threads per block (WPB*16)
#define NB  (BATCH * 25 / WPB)        // 3200 batches
#define NSLICE 8                      // add_lut row slices (64 rows each)

__device__ float          g_cs[NK];
__device__ int            g_order[NK];
__device__ float          g_cent[NK];
__device__ unsigned short g_add16[NK * NK];        // add_lut as u16 (512KB)
__device__ unsigned short g_P1[25 * NK * 8];
__device__ unsigned short g_P2[150 * NK * 16];
__device__ unsigned short g_bias1[NK * 8];
__device__ unsigned short g_bias2[NK * 16];
__device__ unsigned short g_relu[NK];
__device__ unsigned short g_sym[BATCH * 32 * 32];
__device__ unsigned short g_x1[BATCH * 14 * 14 * 6];
__device__ unsigned short g_x2[BATCH * 5 * 5 * 16];

#define PREPN (NK*NK + 25*NK*8 + 150*NK*16 + NK*8 + NK*16 + NK)
#define PREPB ((PREPN + 511) / 512)   // 512-thread prep blocks

// ---------------- prep: packed LUT tables + centroid sort (merged) -----------
// Blocks [0, PREPB) convert/pack tables; block PREPB (512 threads) does the
// stable centroid argsort. Independent outputs -> safe in one launch.
__global__ void __launch_bounds__(512) k_prep0(
    const float* __restrict__ centroid_lut,
    const int* __restrict__ conv_lut, const int* __restrict__ add_lut,
    const int* __restrict__ c1w, const int* __restrict__ c2w,
    const int* __restrict__ b1, const int* __restrict__ b2,
    const int* __restrict__ relu) {
    if (blockIdx.x == PREPB) {        // centroid sort block
        __shared__ float c[NK];
        int t = threadIdx.x;          // 512 threads = NK
        c[t] = centroid_lut[t];
        __syncthreads();
        float ci = c[t];
        int rank = 0;
        for (int j = 0; j < NK; j++) {
            float cj = c[j];
            rank += (cj < ci) || (cj == ci && j < t);   // stable argsort
        }
        g_cs[rank]    = ci;
        g_order[rank] = t;
        g_cent[t]     = ci;
        return;
    }
    int i = blockIdx.x * 512 + threadIdx.x;
    if (i < NK * NK) { g_add16[i] = (unsigned short)add_lut[i]; return; }
    i -= NK * NK;
    if (i < 25 * NK * 8) {
        int oc = i & 7; int s = (i >> 3) & (NK - 1); int j = i >> 12;
        int occ = oc < 6 ? oc : 5;
        g_P1[i] = (unsigned short)conv_lut[s * NK + c1w[j * 6 + occ]];
        return;
    }
    i -= 25 * NK * 8;
    if (i < 150 * NK * 16) {
        int oc = i & 15; int s = (i >> 4) & (NK - 1); int j = i >> 13;
        g_P2[i] = (unsigned short)conv_lut[s * NK + c2w[j * 16 + oc]];
        return;
    }
    i -= 150 * NK * 16;
    if (i < NK * 8) {
        int oc = i & 7; int s = i >> 3; int occ = oc < 6 ? oc : 5;
        g_bias1[i] = (unsigned short)b1[s * 6 + occ];
        return;
    }
    i -= NK * 8;
    if (i < NK * 16) { g_bias2[i] = (unsigned short)b2[i]; return; }
    i -= NK * 16;
    if (i < NK) g_relu[i] = (unsigned short)relu[i];
}

// ---------------- discretize ----------------
__global__ void k_disc(const float* __restrict__ x) {
    __shared__ float cs[NK];
    __shared__ int   ord[NK];
    int t = threadIdx.x;
    for (int i = t; i < NK; i += blockDim.x) { cs[i] = g_cs[i]; ord[i] = g_order[i]; }
    __syncthreads();
    int idx = blockIdx.x * blockDim.x + t;
    float v = x[idx];
    int lo = 0, hi = NK;
    #pragma unroll
    for (int it = 0; it < 9; it++) {
        int m = (lo + hi) >> 1;
        if (cs[m] < v) lo = m + 1; else hi = m;
    }
    int l = lo - 1; if (l < 0) l = 0;
    int h = lo;     if (h > NK - 1) h = NK - 1;
    float dl = fabsf(v - cs[l]);
    float dh = fabsf(v - cs[h]);
    g_sym[idx] = (unsigned short)ord[(dl <= dh) ? l : h];
}

// ---------------- conv1: register bitonic sort + LUT fold ----------------
__global__ void __launch_bounds__(128) k_conv1() {
    int id  = blockIdx.x * 128 + threadIdx.x;
    int oc  = id % 6;
    int win = id / 6;
    int b   = win / 196;
    int r   = win % 196;
    int oy  = r / 14, ox = r % 14;

    const unsigned short* base = g_sym + (b * 32 + oy * 2) * 32 + ox * 2;
    unsigned v[32];
    #pragma unroll
    for (int ky = 0; ky < 5; ky++)
        #pragma unroll
        for (int kx = 0; kx < 5; kx++) {
            unsigned s = base[ky * 32 + kx];
            v[ky * 5 + kx] = g_P1[((ky * 5 + kx) * NK + s) * 8 + oc];
        }
    #pragma unroll
    for (int i = 25; i < 32; i++) v[i] = 0xFFFFu;

    #pragma unroll
    for (int k2 = 2; k2 <= 32; k2 <<= 1) {
        #pragma unroll
        for (int j = k2 >> 1; j > 0; j >>= 1) {
            #pragma unroll
            for (int i = 0; i < 32; i++) {
                int l = i ^ j;
                if (l > i) {
                    bool up = ((i & k2) == 0);
                    unsigned a = v[i], c = v[l];
                    unsigned mn = a < c ? a : c;
                    unsigned mx = a < c ? c : a;
                    v[i] = up ? mn : mx;
                    v[l] = up ? mx : mn;
                }
            }
        }
    }

    unsigned acc = v[0];
    #pragma unroll
    for (int i = 1; i < 25; i++) acc = g_add16[v[i] * NK + acc];

    unsigned t2 = g_bias1[acc * 8 + oc];
    g_x1[((b * 14 + oy) * 14 + ox) * 6 + oc] = g_relu[t2];
}

// ---------------- conv2: persistent, add_lut slices in SMEM (R8 fold) --------
// 148 blocks x 512 threads, 1 chain/thread/batch.
// smem: tbl 64KB | hist 128KB (nibble counts, per-thread column) | syms 9.5KB.
// Fold: proven branchy cursor loop over per-range submask `cur`.
// Slice reloads register-prefetched so the L2 transfer overlaps the fold.
__global__ void __launch_bounds__(C2T, 1) k_conv2p() {
    extern __shared__ unsigned char sm[];
    unsigned short* tbl  = (unsigned short*)sm;                        // 65536 B
    unsigned int*   hist = (unsigned int*)(sm + 65536);                // 131072 B
    unsigned short* syms = (unsigned short*)(sm + 65536 + 131072);     // 9728 B
    int tid = threadIdx.x;
    int win = tid >> 4, oc = tid & 15;
    unsigned int* hcol = hist + tid;

    for (int batch = blockIdx.x; batch < NB; batch += gridDim.x) {
        // zero own hist column (private: no sync needed)
        #pragma unroll
        for (int g = 0; g < 64; g++) hcol[g * C2T] = 0;

        // cooperative sym staging for WPB windows
        for (int i = tid; i < WPB * 150; i += C2T) {
            int w = i / 150, j = i % 150;
            int wg = batch * WPB + w;
            int b = wg / 25, p = wg % 25;
            int oy = p / 5, ox = p % 5;
            int kk = j / 6, c = j % 6;
            int ky = kk / 5, kx = kk % 5;
            syms[w * 152 + j] =
                g_x1[((b * 14 + oy * 2 + ky) * 14 + (ox * 2 + kx)) * 6 + c];
        }

        // prefetch slice 0 into registers (overlaps staging barrier + phase A)
        uint4 pf[8];
        {
            const uint4* src = (const uint4*)(g_add16);
            #pragma unroll
            for (int i = 0; i < 8; i++) pf[i] = src[i * C2T + tid];
        }
        __syncthreads();

        // phase A: product gather (MLP=10) + nibble histogram + group mask
        const unsigned short* sy = syms + win * 152;
        unsigned long long mask = 0ull;
        #pragma unroll 1
        for (int j0 = 0; j0 < 150; j0 += 10) {
            unsigned sv[10];
            #pragma unroll
            for (int u = 0; u < 10; u++) sv[u] = sy[j0 + u];
            unsigned vv[10];
            #pragma unroll
            for (int u = 0; u < 10; u++)
                vv[u] = g_P2[((j0 + u) * NK + sv[u]) * 16 + oc];
            #pragma unroll
            for (int u = 0; u < 10; u++) {
                unsigned v = vv[u];
                hcol[(v >> 3) * C2T] += 1u << (4 * (v & 7));
                mask |= 1ull << (v >> 3);
            }
        }

        // fold in ascending order across NSLICE row-ranges of the add table
        unsigned acc = 0xFFFFFFFFu;                     // sentinel: first value
        for (int r = 0; r < NSLICE; r++) {
            __syncthreads();                            // prior fold / phase A done
            {   // commit prefetched slice r to smem
                uint4* dst = (uint4*)tbl;
                #pragma unroll
                for (int i = 0; i < 8; i++) dst[i * C2T + tid] = pf[i];
            }
            __syncthreads();
            if (r + 1 < NSLICE) {                       // prefetch slice r+1 (hidden under fold)
                const uint4* src = (const uint4*)(g_add16 + (r + 1) * 32768);
                #pragma unroll
                for (int i = 0; i < 8; i++) pf[i] = src[i * C2T + tid];
            }

            // split off this range's groups (r==7 covers all remaining; avoids 1<<64)
            unsigned long long cur =
                (r == NSLICE - 1) ? mask : (mask & ((1ull << (8 * (r + 1))) - 1ull));
            mask &= ~cur;

            unsigned w = 0;
            int g = 0;
            while (true) {
                if (w == 0) {                           // pull next nonzero group
                    if (cur == 0) break;
                    g = __ffsll((long long)cur) - 1;
                    cur &= cur - 1;
                    w = hcol[g * C2T];
                }
                int bit  = __ffs((int)w) - 1;
                int slot = bit >> 2;
                unsigned v = (unsigned)(g * 8 + slot);
                w -= 1u << (slot << 2);
                unsigned a  = acc & 511u;               // sentinel-safe index
                unsigned nv = tbl[((v & 63u) << 9) + a];
                acc = (acc > 511u) ? v : nv;
            }
        }

        unsigned t2 = g_bias2[acc * 16 + oc];
        int wg = batch * WPB + win;
        g_x2[wg * 16 + oc] = g_relu[t2];
        __syncthreads();                                // smem reuse next batch
    }
}

// ---------------- FC stack + softmax ----------------
__global__ void __launch_bounds__(128) k_fc(
    const float* __restrict__ w1, const float* __restrict__ fb1,
    const float* __restrict__ w2, const float* __restrict__ fb2,
    const float* __restrict__ w3, const float* __restrict__ fb3,
    float* __restrict__ out) {
    __shared__ __align__(16) float feat[400];
    __shared__ __align__(16) float h1[120];
    __shared__ __align__(16) float h2[84];
    __shared__ float lg[10];
    int b = blockIdx.x, t = threadIdx.x;

    for (int i = t; i < 400; i += 128) {
        int c = i / 25, r = i % 25;
        unsigned s = g_x2[(b * 25 + r) * 16 + c];
        feat[i] = g_cent[s];
    }
    __syncthreads();

    if (t < 120) {
        float acc = fb1[t];
        const float4* wr = (const float4*)(w1 + t * 400);
        const float4* fr = (const float4*)feat;
        #pragma unroll 5
        for (int k = 0; k < 100; k++) {
            float4 a = wr[k], f = fr[k];
            acc += a.x * f.x + a.y * f.y + a.z * f.z + a.w * f.w;
        }
        h1[t] = 1.f / (1.f + expf(-acc));
    }
    __syncthreads();
    if (t < 84) {
        float acc = fb2[t];
        const float4* wr = (const float4*)(w2 + t * 120);
        const float4* fr = (const float4*)h1;
        #pragma unroll 5
        for (int k = 0; k < 30; k++) {
            float4 a = wr[k], f = fr[k];
            acc += a.x * f.x + a.y * f.y + a.z * f.z + a.w * f.w;
        }
        h2[t] = 1.f / (1.f + expf(-acc));
    }
    __syncthreads();
    if (t < 10) {
        float acc = fb3[t];
        const float4* wr = (const float4*)(w3 + t * 84);
        const float4* fr = (const float4*)h2;
        #pragma unroll
        for (int k = 0; k < 21; k++) {
            float4 a = wr[k], f = fr[k];
            acc += a.x * f.x + a.y * f.y + a.z * f.z + a.w * f.w;
        }
        lg[t] = acc;
    }
    __syncthreads();
    if (t < 10) {
        float m = lg[0];
        #pragma unroll
        for (int i = 1; i < 10; i++) m = fmaxf(m, lg[i]);
        float s = 0.f;
        #pragma unroll
        for (int i = 0; i < 10; i++) s += expf(lg[i] - m);
        out[b * 10 + t] = expf(lg[t] - m) / s;
    }
}

// ---------------- launch ----------------
extern "C" void kernel_launch(void* const* d_in, const int* in_sizes, int n_in,
                              void* d_out, int out_size) {
    const float* x        = (const float*)d_in[0];
    const float* cent     = (const float*)d_in[1];
    const int*   c1w      = (const int*)d_in[2];
    const int*   c2w      = (const int*)d_in[3];
    const int*   conv_lut = (const int*)d_in[4];
    const int*   add_lut  = (const int*)d_in[5];
    const int*   b1l      = (const int*)d_in[6];
    const int*   b2l      = (const int*)d_in[7];
    const int*   relu     = (const int*)d_in[8];
    const float* w1  = (const float*)d_in[9];
    const float* fb1 = (const float*)d_in[10];
    const float* w2  = (const float*)d_in[11];
    const float* fb2 = (const float*)d_in[12];
    const float* w3  = (const float*)d_in[13];
    const float* fb3 = (const float*)d_in[14];
    float* out = (float*)d_out;

    const int SMEM_C2 = 65536 + 131072 + 9728;   // 206336 B
    cudaFuncSetAttribute(k_conv2p, cudaFuncAttributeMaxDynamicSharedMemorySize, SMEM_C2);

    // launch order puts k_conv2p at slot 4 (the slot ncu captures)
    k_prep0<<<PREPB + 1, 512>>>(cent, conv_lut, add_lut, c1w, c2w, b1l, b2l, relu);
    k_disc<<<(BATCH * 1024) / 256, 256>>>(x);
    k_conv1<<<(BATCH * 196 * 6) / 128, 128>>>();
    k_conv2p<<<148, C2T, SMEM_C2>>>();
    k_fc<<<BATCH, 128>>>(w1, fb1, w2, fb2, w3, fb3, out);
}

// round 13
// speedup vs baseline: 1.0982x; 1.0512x over previous
#include <cuda_runtime.h>
#include <math.h>

// ---------------- static device scratch (no allocations allowed) ----------------
#define NK 512
#define BATCH 4096
#define WPB 32                        // windows per conv2 batch
#define C2T 512                       // conv2 threads per block (WPB*16)
#define NB  (BATCH * 25 / WPB)        // 3200 batches
#define NSLICE 8                      // add_lut row slices (64 rows each)

__device__ float          g_cs[NK];
__device__ int            g_order[NK];
__device__ float          g_cent[NK];
__device__ unsigned short g_add16[NK * NK];        // add_lut as u16 (512KB)
__device__ unsigned short g_P1[25 * NK * 8];
__device__ unsigned short g_P2[150 * NK * 16];
__device__ unsigned short g_bias1[NK * 8];
__device__ unsigned short g_bias2[NK * 16];
__device__ unsigned short g_relu[NK];
__device__ unsigned short g_sym[BATCH * 32 * 32];
__device__ unsigned short g_x1[BATCH * 14 * 14 * 6];
__device__ unsigned short g_x2[BATCH * 5 * 5 * 16];

#define PREPN (NK*NK + 25*NK*8 + 150*NK*16 + NK*8 + NK*16 + NK)
#define PREPB ((PREPN + 511) / 512)   // 512-thread prep blocks

// ---------------- prep: packed LUT tables + centroid sort (merged) -----------
__global__ void __launch_bounds__(512) k_prep0(
    const float* __restrict__ centroid_lut,
    const int* __restrict__ conv_lut, const int* __restrict__ add_lut,
    const int* __restrict__ c1w, const int* __restrict__ c2w,
    const int* __restrict__ b1, const int* __restrict__ b2,
    const int* __restrict__ relu) {
    if (blockIdx.x == PREPB) {        // centroid sort block
        __shared__ float c[NK];
        int t = threadIdx.x;          // 512 threads = NK
        c[t] = centroid_lut[t];
        __syncthreads();
        float ci = c[t];
        int rank = 0;
        for (int j = 0; j < NK; j++) {
            float cj = c[j];
            rank += (cj < ci) || (cj == ci && j < t);   // stable argsort
        }
        g_cs[rank]    = ci;
        g_order[rank] = t;
        g_cent[t]     = ci;
        return;
    }
    int i = blockIdx.x * 512 + threadIdx.x;
    if (i < NK * NK) { g_add16[i] = (unsigned short)add_lut[i]; return; }
    i -= NK * NK;
    if (i < 25 * NK * 8) {
        int oc = i & 7; int s = (i >> 3) & (NK - 1); int j = i >> 12;
        int occ = oc < 6 ? oc : 5;
        g_P1[i] = (unsigned short)conv_lut[s * NK + c1w[j * 6 + occ]];
        return;
    }
    i -= 25 * NK * 8;
    if (i < 150 * NK * 16) {
        int oc = i & 15; int s = (i >> 4) & (NK - 1); int j = i >> 13;
        g_P2[i] = (unsigned short)conv_lut[s * NK + c2w[j * 16 + oc]];
        return;
    }
    i -= 150 * NK * 16;
    if (i < NK * 8) {
        int oc = i & 7; int s = i >> 3; int occ = oc < 6 ? oc : 5;
        g_bias1[i] = (unsigned short)b1[s * 6 + occ];
        return;
    }
    i -= NK * 8;
    if (i < NK * 16) { g_bias2[i] = (unsigned short)b2[i]; return; }
    i -= NK * 16;
    if (i < NK) g_relu[i] = (unsigned short)relu[i];
}

// ---------------- discretize ----------------
__global__ void k_disc(const float* __restrict__ x) {
    __shared__ float cs[NK];
    __shared__ int   ord[NK];
    int t = threadIdx.x;
    for (int i = t; i < NK; i += blockDim.x) { cs[i] = g_cs[i]; ord[i] = g_order[i]; }
    __syncthreads();
    int idx = blockIdx.x * blockDim.x + t;
    float v = x[idx];
    int lo = 0, hi = NK;
    #pragma unroll
    for (int it = 0; it < 9; it++) {
        int m = (lo + hi) >> 1;
        if (cs[m] < v) lo = m + 1; else hi = m;
    }
    int l = lo - 1; if (l < 0) l = 0;
    int h = lo;     if (h > NK - 1) h = NK - 1;
    float dl = fabsf(v - cs[l]);
    float dh = fabsf(v - cs[h]);
    g_sym[idx] = (unsigned short)ord[(dl <= dh) ? l : h];
}

// ---------------- conv1: register bitonic sort + LUT fold ----------------
__global__ void __launch_bounds__(128) k_conv1() {
    int id  = blockIdx.x * 128 + threadIdx.x;
    int oc  = id % 6;
    int win = id / 6;
    int b   = win / 196;
    int r   = win % 196;
    int oy  = r / 14, ox = r % 14;

    const unsigned short* base = g_sym + (b * 32 + oy * 2) * 32 + ox * 2;
    unsigned v[32];
    #pragma unroll
    for (int ky = 0; ky < 5; ky++)
        #pragma unroll
        for (int kx = 0; kx < 5; kx++) {
            unsigned s = base[ky * 32 + kx];
            v[ky * 5 + kx] = g_P1[((ky * 5 + kx) * NK + s) * 8 + oc];
        }
    #pragma unroll
    for (int i = 25; i < 32; i++) v[i] = 0xFFFFu;

    #pragma unroll
    for (int k2 = 2; k2 <= 32; k2 <<= 1) {
        #pragma unroll
        for (int j = k2 >> 1; j > 0; j >>= 1) {
            #pragma unroll
            for (int i = 0; i < 32; i++) {
                int l = i ^ j;
                if (l > i) {
                    bool up = ((i & k2) == 0);
                    unsigned a = v[i], c = v[l];
                    unsigned mn = a < c ? a : c;
                    unsigned mx = a < c ? c : a;
                    v[i] = up ? mn : mx;
                    v[l] = up ? mx : mn;
                }
            }
        }
    }

    unsigned acc = v[0];
    #pragma unroll
    for (int i = 1; i < 25; i++) acc = g_add16[v[i] * NK + acc];

    unsigned t2 = g_bias1[acc * 8 + oc];
    g_x1[((b * 14 + oy) * 14 + ox) * 6 + oc] = g_relu[t2];
}

// ---------------- conv2: persistent, add_lut slices in SMEM ----------------
// 148 blocks x 512 threads, 1 chain/thread/batch.
// smem: tbl 64KB | hist 128KB (nibble counts, per-thread column) | syms 9.5KB.
// Fold: branchy cursor loop; per-range group set = BYTE r of the 64-bit mask
// -> all mask ops are 8/32-bit; per-range constants hoisted (cheap iteration).
// Slice reloads register-prefetched so the L2 transfer overlaps the fold.
__global__ void __launch_bounds__(C2T, 1) k_conv2p() {
    extern __shared__ unsigned char sm[];
    unsigned short* tbl  = (unsigned short*)sm;                        // 65536 B
    unsigned int*   hist = (unsigned int*)(sm + 65536);                // 131072 B
    unsigned short* syms = (unsigned short*)(sm + 65536 + 131072);     // 9728 B
    int tid = threadIdx.x;
    int win = tid >> 4, oc = tid & 15;
    unsigned int* hcol = hist + tid;

    for (int batch = blockIdx.x; batch < NB; batch += gridDim.x) {
        // zero own hist column (private: no sync needed)
        #pragma unroll
        for (int g = 0; g < 64; g++) hcol[g * C2T] = 0;

        // cooperative sym staging for WPB windows
        for (int i = tid; i < WPB * 150; i += C2T) {
            int w = i / 150, j = i % 150;
            int wg = batch * WPB + w;
            int b = wg / 25, p = wg % 25;
            int oy = p / 5, ox = p % 5;
            int kk = j / 6, c = j % 6;
            int ky = kk / 5, kx = kk % 5;
            syms[w * 152 + j] =
                g_x1[((b * 14 + oy * 2 + ky) * 14 + (ox * 2 + kx)) * 6 + c];
        }

        // prefetch slice 0 into registers (overlaps staging barrier + phase A)
        uint4 pf[8];
        {
            const uint4* src = (const uint4*)(g_add16);
            #pragma unroll
            for (int i = 0; i < 8; i++) pf[i] = src[i * C2T + tid];
        }
        __syncthreads();

        // phase A: product gather (MLP=10) + nibble histogram + group mask
        const unsigned short* sy = syms + win * 152;
        unsigned long long mask = 0ull;
        #pragma unroll 1
        for (int j0 = 0; j0 < 150; j0 += 10) {
            unsigned sv[10];
            #pragma unroll
            for (int u = 0; u < 10; u++) sv[u] = sy[j0 + u];
            unsigned vv[10];
            #pragma unroll
            for (int u = 0; u < 10; u++)
                vv[u] = g_P2[((j0 + u) * NK + sv[u]) * 16 + oc];
            #pragma unroll
            for (int u = 0; u < 10; u++) {
                unsigned v = vv[u];
                hcol[(v >> 3) * C2T] += 1u << (4 * (v & 7));
                mask |= 1ull << (v >> 3);
            }
        }

        // fold in ascending order across NSLICE row-ranges of the add table
        unsigned acc = 0xFFFFFFFFu;                     // sentinel: first value
        for (int r = 0; r < NSLICE; r++) {
            __syncthreads();                            // prior fold / phase A done
            {   // commit prefetched slice r to smem
                uint4* dst = (uint4*)tbl;
                #pragma unroll
                for (int i = 0; i < 8; i++) dst[i * C2T + tid] = pf[i];
            }
            __syncthreads();
            if (r + 1 < NSLICE) {                       // prefetch slice r+1 (hidden under fold)
                const uint4* src = (const uint4*)(g_add16 + (r + 1) * 32768);
                #pragma unroll
                for (int i = 0; i < 8; i++) pf[i] = src[i * C2T + tid];
            }

            // this range's groups = byte r of mask (groups 8r..8r+7)
            unsigned cur   = (unsigned)(mask >> (8 * r)) & 0xFFu;
            unsigned vbase = (unsigned)(r << 6);
            unsigned int* hrow = hcol + (8 * r) * C2T;

            unsigned w = 0;
            unsigned row8 = 0;
            while (true) {
                if (w == 0) {                           // pull next nonzero group
                    if (cur == 0) break;
                    int g2 = __ffs(cur) - 1;
                    cur &= cur - 1u;
                    w = hrow[g2 * C2T];
                    row8 = (unsigned)(g2 << 3);
                }
                int bit  = __ffs((int)w) - 1;
                int slot = bit >> 2;
                unsigned row = row8 + slot;             // row within 64-row slice
                w -= 1u << (slot << 2);
                unsigned a  = acc & 511u;               // sentinel-safe index
                unsigned nv = tbl[(row << 9) + a];
                acc = (acc > 511u) ? (vbase + row) : nv;
            }
        }

        unsigned t2 = g_bias2[acc * 16 + oc];
        int wg = batch * WPB + win;
        g_x2[wg * 16 + oc] = g_relu[t2];
        __syncthreads();                                // smem reuse next batch
    }
}

// ---------------- FC stack + softmax ----------------
__global__ void __launch_bounds__(128) k_fc(
    const float* __restrict__ w1, const float* __restrict__ fb1,
    const float* __restrict__ w2, const float* __restrict__ fb2,
    const float* __restrict__ w3, const float* __restrict__ fb3,
    float* __restrict__ out) {
    __shared__ __align__(16) float feat[400];
    __shared__ __align__(16) float h1[120];
    __shared__ __align__(16) float h2[84];
    __shared__ float lg[10];
    int b = blockIdx.x, t = threadIdx.x;

    for (int i = t; i < 400; i += 128) {
        int c = i / 25, r = i % 25;
        unsigned s = g_x2[(b * 25 + r) * 16 + c];
        feat[i] = g_cent[s];
    }
    __syncthreads();

    if (t < 120) {
        float acc = fb1[t];
        const float4* wr = (const float4*)(w1 + t * 400);
        const float4* fr = (const float4*)feat;
        #pragma unroll 5
        for (int k = 0; k < 100; k++) {
            float4 a = wr[k], f = fr[k];
            acc += a.x * f.x + a.y * f.y + a.z * f.z + a.w * f.w;
        }
        h1[t] = 1.f / (1.f + expf(-acc));
    }
    __syncthreads();
    if (t < 84) {
        float acc = fb2[t];
        const float4* wr = (const float4*)(w2 + t * 120);
        const float4* fr = (const float4*)h1;
        #pragma unroll 5
        for (int k = 0; k < 30; k++) {
            float4 a = wr[k], f = fr[k];
            acc += a.x * f.x + a.y * f.y + a.z * f.z + a.w * f.w;
        }
        h2[t] = 1.f / (1.f + expf(-acc));
    }
    __syncthreads();
    if (t < 10) {
        float acc = fb3[t];
        const float4* wr = (const float4*)(w3 + t * 84);
        const float4* fr = (const float4*)h2;
        #pragma unroll
        for (int k = 0; k < 21; k++) {
            float4 a = wr[k], f = fr[k];
            acc += a.x * f.x + a.y * f.y + a.z * f.z + a.w * f.w;
        }
        lg[t] = acc;
    }
    __syncthreads();
    if (t < 10) {
        float m = lg[0];
        #pragma unroll
        for (int i = 1; i < 10; i++) m = fmaxf(m, lg[i]);
        float s = 0.f;
        #pragma unroll
        for (int i = 0; i < 10; i++) s += expf(lg[i] - m);
        out[b * 10 + t] = expf(lg[t] - m) / s;
    }
}

// ---------------- launch ----------------
extern "C" void kernel_launch(void* const* d_in, const int* in_sizes, int n_in,
                              void* d_out, int out_size) {
    const float* x        = (const float*)d_in[0];
    const float* cent     = (const float*)d_in[1];
    const int*   c1w      = (const int*)d_in[2];
    const int*   c2w      = (const int*)d_in[3];
    const int*   conv_lut = (const int*)d_in[4];
    const int*   add_lut  = (const int*)d_in[5];
    const int*   b1l      = (const int*)d_in[6];
    const int*   b2l      = (const int*)d_in[7];
    const int*   relu     = (const int*)d_in[8];
    const float* w1  = (const float*)d_in[9];
    const float* fb1 = (const float*)d_in[10];
    const float* w2  = (const float*)d_in[11];
    const float* fb2 = (const float*)d_in[12];
    const float* w3  = (const float*)d_in[13];
    const float* fb3 = (const float*)d_in[14];
    float* out = (float*)d_out;

    const int SMEM_C2 = 65536 + 131072 + 9728;   // 206336 B
    cudaFuncSetAttribute(k_conv2p, cudaFuncAttributeMaxDynamicSharedMemorySize, SMEM_C2);

    // launch order keeps k_conv2p at slot 4 (the slot ncu captures)
    k_prep0<<<PREPB + 1, 512>>>(cent, conv_lut, add_lut, c1w, c2w, b1l, b2l, relu);
    k_disc<<<(BATCH * 1024) / 256, 256>>>(x);
    k_conv1<<<(BATCH * 196 * 6) / 128, 128>>>();
    k_conv2p<<<148, C2T, SMEM_C2>>>();
    k_fc<<<BATCH, 128>>>(w1, fb1, w2, fb2, w3, fb3, out);
}

// round 17
// speedup vs baseline: 1.1269x; 1.0261x over previous
#include <cuda_runtime.h>
#include <math.h>

// ---------------- static device scratch (no allocations allowed) ----------------
#define NK 512
#define BATCH 4096
#define WPB 32                        // windows per conv2 batch
#define C2T 512                       // conv2 threads per block (WPB*16)
#define NB  (BATCH * 25 / WPB)        // 3200 batches
#define NSLICE 8                      // add_lut row slices (64 rows each)

__device__ float          g_cs[NK];
__device__ int            g_order[NK];
__device__ float          g_cent[NK];
__device__ unsigned short g_add16[NK * NK];        // add_lut as u16 (512KB)
__device__ unsigned short g_P1[25 * NK * 8];
__device__ unsigned short g_P2[150 * NK * 16];
__device__ unsigned short g_bias1[NK * 8];
__device__ unsigned short g_bias2[NK * 16];
__device__ unsigned short g_relu[NK];
__device__ unsigned short g_sym[BATCH * 32 * 32];
__device__ unsigned short g_x1[BATCH * 14 * 14 * 6];
__device__ unsigned short g_x2[BATCH * 5 * 5 * 16];

#define PREPN (NK*NK + 25*NK*8 + 150*NK*16 + NK*8 + NK*16 + NK)
#define PREPB ((PREPN + 511) / 512)   // 512-thread prep blocks

// ---------------- prep: packed LUT tables + centroid sort (merged) -----------
__global__ void __launch_bounds__(512) k_prep0(
    const float* __restrict__ centroid_lut,
    const int* __restrict__ conv_lut, const int* __restrict__ add_lut,
    const int* __restrict__ c1w, const int* __restrict__ c2w,
    const int* __restrict__ b1, const int* __restrict__ b2,
    const int* __restrict__ relu) {
    if (blockIdx.x == PREPB) {        // centroid sort block
        __shared__ float c[NK];
        int t = threadIdx.x;          // 512 threads = NK
        c[t] = centroid_lut[t];
        __syncthreads();
        float ci = c[t];
        int rank = 0;
        for (int j = 0; j < NK; j++) {
            float cj = c[j];
            rank += (cj < ci) || (cj == ci && j < t);   // stable argsort
        }
        g_cs[rank]    = ci;
        g_order[rank] = t;
        g_cent[t]     = ci;
        return;
    }
    int i = blockIdx.x * 512 + threadIdx.x;
    if (i < NK * NK) { g_add16[i] = (unsigned short)add_lut[i]; return; }
    i -= NK * NK;
    if (i < 25 * NK * 8) {
        int oc = i & 7; int s = (i >> 3) & (NK - 1); int j = i >> 12;
        int occ = oc < 6 ? oc : 5;
        g_P1[i] = (unsigned short)conv_lut[s * NK + c1w[j * 6 + occ]];
        return;
    }
    i -= 25 * NK * 8;
    if (i < 150 * NK * 16) {
        int oc = i & 15; int s = (i >> 4) & (NK - 1); int j = i >> 13;
        g_P2[i] = (unsigned short)conv_lut[s * NK + c2w[j * 16 + oc]];
        return;
    }
    i -= 150 * NK * 16;
    if (i < NK * 8) {
        int oc = i & 7; int s = i >> 3; int occ = oc < 6 ? oc : 5;
        g_bias1[i] = (unsigned short)b1[s * 6 + occ];
        return;
    }
    i -= NK * 8;
    if (i < NK * 16) { g_bias2[i] = (unsigned short)b2[i]; return; }
    i -= NK * 16;
    if (i < NK) g_relu[i] = (unsigned short)relu[i];
}

// ---------------- discretize ----------------
__global__ void k_disc(const float* __restrict__ x) {
    __shared__ float cs[NK];
    __shared__ int   ord[NK];
    int t = threadIdx.x;
    for (int i = t; i < NK; i += blockDim.x) { cs[i] = g_cs[i]; ord[i] = g_order[i]; }
    __syncthreads();
    int idx = blockIdx.x * blockDim.x + t;
    float v = x[idx];
    int lo = 0, hi = NK;
    #pragma unroll
    for (int it = 0; it < 9; it++) {
        int m = (lo + hi) >> 1;
        if (cs[m] < v) lo = m + 1; else hi = m;
    }
    int l = lo - 1; if (l < 0) l = 0;
    int h = lo;     if (h > NK - 1) h = NK - 1;
    float dl = fabsf(v - cs[l]);
    float dh = fabsf(v - cs[h]);
    g_sym[idx] = (unsigned short)ord[(dl <= dh) ? l : h];
}

// ---------------- conv1: register bitonic sort + LUT fold ----------------
__global__ void __launch_bounds__(128) k_conv1() {
    int id  = blockIdx.x * 128 + threadIdx.x;
    int oc  = id % 6;
    int win = id / 6;
    int b   = win / 196;
    int r   = win % 196;
    int oy  = r / 14, ox = r % 14;

    const unsigned short* base = g_sym + (b * 32 + oy * 2) * 32 + ox * 2;
    unsigned v[32];
    #pragma unroll
    for (int ky = 0; ky < 5; ky++)
        #pragma unroll
        for (int kx = 0; kx < 5; kx++) {
            unsigned s = base[ky * 32 + kx];
            v[ky * 5 + kx] = g_P1[((ky * 5 + kx) * NK + s) * 8 + oc];
        }
    #pragma unroll
    for (int i = 25; i < 32; i++) v[i] = 0xFFFFu;

    #pragma unroll
    for (int k2 = 2; k2 <= 32; k2 <<= 1) {
        #pragma unroll
        for (int j = k2 >> 1; j > 0; j >>= 1) {
            #pragma unroll
            for (int i = 0; i < 32; i++) {
                int l = i ^ j;
                if (l > i) {
                    bool up = ((i & k2) == 0);
                    unsigned a = v[i], c = v[l];
                    unsigned mn = a < c ? a : c;
                    unsigned mx = a < c ? c : a;
                    v[i] = up ? mn : mx;
                    v[l] = up ? mx : mn;
                }
            }
        }
    }

    unsigned acc = v[0];
    #pragma unroll
    for (int i = 1; i < 25; i++) acc = g_add16[v[i] * NK + acc];

    unsigned t2 = g_bias1[acc * 8 + oc];
    g_x1[((b * 14 + oy) * 14 + ox) * 6 + oc] = g_relu[t2];
}

// ---------------- conv2: persistent, add_lut slices in SMEM ----------------
// 148 blocks x 512 threads, 1 chain/thread/batch.
// smem: tbl 64KB | hist 128KB (nibble counts, per-thread column) | syms 9.5KB.
// Hist nibbles REVERSED within each group word (value v -> slot 7-(v&7)), so
// the lowest remaining value = HIGHEST set bit -> single-FLO extraction.
// Fold: uniform 8-group walk per range (no per-lane group cursor, no mask),
// divergent-count inner while. Slice reloads register-prefetched.
__global__ void __launch_bounds__(C2T, 1) k_conv2p() {
    extern __shared__ unsigned char sm[];
    unsigned short* tbl  = (unsigned short*)sm;                        // 65536 B
    unsigned int*   hist = (unsigned int*)(sm + 65536);                // 131072 B
    unsigned short* syms = (unsigned short*)(sm + 65536 + 131072);     // 9728 B
    int tid = threadIdx.x;
    int win = tid >> 4, oc = tid & 15;
    unsigned int* hcol = hist + tid;

    for (int batch = blockIdx.x; batch < NB; batch += gridDim.x) {
        // zero own hist column (private: no sync needed)
        #pragma unroll
        for (int g = 0; g < 64; g++) hcol[g * C2T] = 0;

        // cooperative sym staging for WPB windows
        for (int i = tid; i < WPB * 150; i += C2T) {
            int w = i / 150, j = i % 150;
            int wg = batch * WPB + w;
            int b = wg / 25, p = wg % 25;
            int oy = p / 5, ox = p % 5;
            int kk = j / 6, c = j % 6;
            int ky = kk / 5, kx = kk % 5;
            syms[w * 152 + j] =
                g_x1[((b * 14 + oy * 2 + ky) * 14 + (ox * 2 + kx)) * 6 + c];
        }

        // prefetch slice 0 into registers (overlaps staging barrier + phase A)
        uint4 pf[8];
        {
            const uint4* src = (const uint4*)(g_add16);
            #pragma unroll
            for (int i = 0; i < 8; i++) pf[i] = src[i * C2T + tid];
        }
        __syncthreads();

        // phase A: product gather (MLP=10) + reversed-slot nibble histogram
        const unsigned short* sy = syms + win * 152;
        #pragma unroll 1
        for (int j0 = 0; j0 < 150; j0 += 10) {
            unsigned sv[10];
            #pragma unroll
            for (int u = 0; u < 10; u++) sv[u] = sy[j0 + u];
            unsigned vv[10];
            #pragma unroll
            for (int u = 0; u < 10; u++)
                vv[u] = g_P2[((j0 + u) * NK + sv[u]) * 16 + oc];
            #pragma unroll
            for (int u = 0; u < 10; u++) {
                unsigned v = vv[u];
                hcol[(v >> 3) * C2T] += 1u << (((~v) & 7u) << 2);  // slot 7-(v&7)
            }
        }

        // fold in ascending order across NSLICE row-ranges of the add table
        unsigned acc = 0xFFFFFFFFu;                     // sentinel: first value
        for (int r = 0; r < NSLICE; r++) {
            __syncthreads();                            // prior fold / phase A done
            {   // commit prefetched slice r to smem
                uint4* dst = (uint4*)tbl;
                #pragma unroll
                for (int i = 0; i < 8; i++) dst[i * C2T + tid] = pf[i];
            }
            __syncthreads();
            if (r + 1 < NSLICE) {                       // prefetch slice r+1 (hidden under fold)
                const uint4* src = (const uint4*)(g_add16 + (r + 1) * 32768);
                #pragma unroll
                for (int i = 0; i < 8; i++) pf[i] = src[i * C2T + tid];
            }

            unsigned vbase = (unsigned)(r << 6);
            unsigned int* hrow = hcol + (8 * r) * C2T;

            #pragma unroll 1
            for (int g2 = 0; g2 < 8; g2++) {            // uniform group walk
                unsigned w = hrow[g2 * C2T];
                unsigned rtop = (unsigned)(g2 << 3) + 7u;
                while (w) {
                    int b   = 31 - __clz((int)w);       // FLO: highest set bit
                    int sl  = b >> 2;                   // reversed slot index
                    unsigned row = rtop - (unsigned)sl; // ascending value order
                    w -= 1u << (b & 28);                // decrement that nibble
                    unsigned a  = acc & 511u;           // sentinel-safe index
                    unsigned nv = tbl[(row << 9) + a];
                    acc = (acc > 511u) ? (vbase + row) : nv;
                }
            }
        }

        unsigned t2 = g_bias2[acc * 16 + oc];
        int wg = batch * WPB + win;
        g_x2[wg * 16 + oc] = g_relu[t2];
        __syncthreads();                                // smem reuse next batch
    }
}

// ---------------- FC stack + softmax ----------------
__global__ void __launch_bounds__(128) k_fc(
    const float* __restrict__ w1, const float* __restrict__ fb1,
    const float* __restrict__ w2, const float* __restrict__ fb2,
    const float* __restrict__ w3, const float* __restrict__ fb3,
    float* __restrict__ out) {
    __shared__ __align__(16) float feat[400];
    __shared__ __align__(16) float h1[120];
    __shared__ __align__(16) float h2[84];
    __shared__ float lg[10];
    int b = blockIdx.x, t = threadIdx.x;

    for (int i = t; i < 400; i += 128) {
        int c = i / 25, r = i % 25;
        unsigned s = g_x2[(b * 25 + r) * 16 + c];
        feat[i] = g_cent[s];
    }
    __syncthreads();

    if (t < 120) {
        float acc = fb1[t];
        const float4* wr = (const float4*)(w1 + t * 400);
        const float4* fr = (const float4*)feat;
        #pragma unroll 5
        for (int k = 0; k < 100; k++) {
            float4 a = wr[k], f = fr[k];
            acc += a.x * f.x + a.y * f.y + a.z * f.z + a.w * f.w;
        }
        h1[t] = 1.f / (1.f + expf(-acc));
    }
    __syncthreads();
    if (t < 84) {
        float acc = fb2[t];
        const float4* wr = (const float4*)(w2 + t * 120);
        const float4* fr = (const float4*)h1;
        #pragma unroll 5
        for (int k = 0; k < 30; k++) {
            float4 a = wr[k], f = fr[k];
            acc += a.x * f.x + a.y * f.y + a.z * f.z + a.w * f.w;
        }
        h2[t] = 1.f / (1.f + expf(-acc));
    }
    __syncthreads();
    if (t < 10) {
        float acc = fb3[t];
        const float4* wr = (const float4*)(w3 + t * 84);
        const float4* fr = (const float4*)h2;
        #pragma unroll
        for (int k = 0; k < 21; k++) {
            float4 a = wr[k], f = fr[k];
            acc += a.x * f.x + a.y * f.y + a.z * f.z + a.w * f.w;
        }
        lg[t] = acc;
    }
    __syncthreads();
    if (t < 10) {
        float m = lg[0];
        #pragma unroll
        for (int i = 1; i < 10; i++) m = fmaxf(m, lg[i]);
        float s = 0.f;
        #pragma unroll
        for (int i = 0; i < 10; i++) s += expf(lg[i] - m);
        out[b * 10 + t] = expf(lg[t] - m) / s;
    }
}

// ---------------- launch ----------------
extern "C" void kernel_launch(void* const* d_in, const int* in_sizes, int n_in,
                              void* d_out, int out_size) {
    const float* x        = (const float*)d_in[0];
    const float* cent     = (const float*)d_in[1];
    const int*   c1w      = (const int*)d_in[2];
    const int*   c2w      = (const int*)d_in[3];
    const int*   conv_lut = (const int*)d_in[4];
    const int*   add_lut  = (const int*)d_in[5];
    const int*   b1l      = (const int*)d_in[6];
    const int*   b2l      = (const int*)d_in[7];
    const int*   relu     = (const int*)d_in[8];
    const float* w1  = (const float*)d_in[9];
    const float* fb1 = (const float*)d_in[10];
    const float* w2  = (const float*)d_in[11];
    const float* fb2 = (const float*)d_in[12];
    const float* w3  = (const float*)d_in[13];
    const float* fb3 = (const float*)d_in[14];
    float* out = (float*)d_out;

    const int SMEM_C2 = 65536 + 131072 + 9728;   // 206336 B
    cudaFuncSetAttribute(k_conv2p, cudaFuncAttributeMaxDynamicSharedMemorySize, SMEM_C2);

    // launch order keeps k_conv2p at slot 4 (the slot ncu captures)
    k_prep0<<<PREPB + 1, 512>>>(cent, conv_lut, add_lut, c1w, c2w, b1l, b2l, relu);
    k_disc<<<(BATCH * 1024) / 256, 256>>>(x);
    k_conv1<<<(BATCH * 196 * 6) / 128, 128>>>();
    k_conv2p<<<148, C2T, SMEM_C2>>>();
    k_fc<<<BATCH, 128>>>(w1, fb1, w2, fb2, w3, fb3, out);
}